// round 12
// baseline (speedup 1.0000x reference)
#include <cuda_runtime.h>
#include <cstdint>
#include <cstddef>

// ---------------- problem constants ----------------
#define A_ATOMS 2048
#define DEPTH   64
#define FILT    12
#define KTOT    24576          // A_ATOMS * FILT
#define MN      131072         // A_ATOMS * DEPTH

// ---------------- GEMM config ----------------
#define BM      512
#define BN      64
#define BK      32             // floats of K per stage
#define NSPLIT  37             // 768 BK-units: 28 splits of 21, 9 of 20
#define STAGES  2

#define LDK     36             // padded row length (floats) -> 144 B
#define A_STAGE_BYTES (BM * LDK * 4)        // 73728
#define B_STAGE_BYTES (BN * LDK * 4)        // 9216
#define STAGE_BYTES   (A_STAGE_BYTES + B_STAGE_BYTES)  // 82944
#define SMEM_DYN      (STAGES * STAGE_BYTES)           // 165888

// ---------------- static scratch ----------------
__device__ float g_Wt[64 * KTOT];       // W^T [o][k], RN tf32-rounded
__device__ float g_part[NSPLIT * MN];   // split-K partials (19.4 MB)
__device__ float g_h[MN];               // activation buffer
__device__ float g_BC[2 * MN];          // bond contributions

// ---------------------------------------------------------------------------
// BC[l][a][o] = sum_{f,j} bond[a,f,j] * filters_l[o,f,64+j]
// ---------------------------------------------------------------------------
__global__ __launch_bounds__(64) void bc_kernel(const float* __restrict__ bond,
                                                const float* __restrict__ f0,
                                                const float* __restrict__ f1)
{
    int a = blockIdx.x;
    int o = threadIdx.x;
    __shared__ float bs[24];
    if (o < 24) bs[o] = bond[a * 24 + o];
    __syncthreads();
    float acc0 = 0.f, acc1 = 0.f;
#pragma unroll
    for (int f = 0; f < FILT; f++)
#pragma unroll
        for (int j = 0; j < 2; j++) {
            float b = bs[f * 2 + j];
            acc0 += b * f0[o * 792 + f * 66 + 64 + j];
            acc1 += b * f1[o * 792 + f * 66 + 64 + j];
        }
    g_BC[a * 64 + o]      = acc0;
    g_BC[MN + a * 64 + o] = acc1;
}

// ---------------------------------------------------------------------------
// W^T[o][n*12+f] = round_rn_tf32( sum_d z[n,d] * filt[o,f,d] )
// ---------------------------------------------------------------------------
__global__ __launch_bounds__(256) void w2_kernel(int zsel,
                                                 const float* __restrict__ x,
                                                 const float* __restrict__ filt)
{
    const float* z = zsel ? g_h : x;
    __shared__ float act[8][64];
    __shared__ float fs[64][65];
    __shared__ float outp[64][96];
    const int n0  = blockIdx.x * 8;
    const int tid = threadIdx.x;

    if (tid < 128) {
        int r = tid >> 4, d = (tid & 15) * 4;
        *(float4*)&act[r][d] = *(const float4*)(z + (size_t)(n0 + r) * 64 + d);
    }

    const int ol = tid & 31;
    const int nl = tid >> 5;
    float acc[12][2];

#pragma unroll 1
    for (int f = 0; f < 12; f++) {
        __syncthreads();
        {
            int o  = tid >> 2;
            int d0 = (tid & 3) * 16;
#pragma unroll
            for (int c = 0; c < 8; c++) {
                float2 v = *(const float2*)(filt + (size_t)o * 792 + f * 66 + d0 + c * 2);
                fs[o][d0 + c * 2]     = v.x;
                fs[o][d0 + c * 2 + 1] = v.y;
            }
        }
        __syncthreads();
        float a0 = 0.f, a1 = 0.f;
#pragma unroll 16
        for (int d = 0; d < 64; d++) {
            float av = act[nl][d];
            a0 = fmaf(av, fs[ol * 2][d], a0);
            a1 = fmaf(av, fs[ol * 2 + 1][d], a1);
        }
        acc[f][0] = a0;
        acc[f][1] = a1;
    }

    __syncthreads();
#pragma unroll
    for (int f = 0; f < 12; f++) {
        outp[ol * 2][nl * 12 + f]     = acc[f][0];
        outp[ol * 2 + 1][nl * 12 + f] = acc[f][1];
    }
    __syncthreads();

#pragma unroll
    for (int t = 0; t < 24; t++) {
        int idx = tid + t * 256;
        int row = idx / 96, col = idx % 96;
        float v = outp[row][col];
        uint32_t u;
        asm("cvt.rna.tf32.f32 %0, %1;" : "=r"(u) : "f"(v));
        g_Wt[(size_t)row * KTOT + n0 * 12 + col] = __uint_as_float(u);
    }
}

// ---------------------------------------------------------------------------
// Big GEMM, mma.sync tf32 m16n8k8, single term, A RNA-rounded in-register.
// Warp tile 64x64 (aux/HMMA ratio 1.5): BM=512, 8 warps, each warp owns
// 64 rows x full 64 cols. 2-stage double buffer, 148 CTAs = one wave.
// ---------------------------------------------------------------------------
__global__ __launch_bounds__(256, 1) void gemm_mma(const float* __restrict__ Ag)
{
    extern __shared__ __align__(128) char smem[];

    const int tid  = threadIdx.x;
    const int wid  = tid >> 5;       // warp owns rows [wid*64, wid*64+64)
    const int lane = tid & 31;
    const int lr   = lane >> 2;      // 0..7
    const int lc   = lane & 3;       // 0..3

    const int sp   = blockIdx.y;
    const int kbeg = sp * 20 + (sp < 28 ? sp : 28);   // in BK units
    const int kcnt = 20 + (sp < 28 ? 1 : 0);
    const int m0   = blockIdx.x * BM;

    const float* Abase = Ag + (size_t)m0 * KTOT + (size_t)kbeg * BK;
    const float* Bbase = g_Wt + (size_t)kbeg * BK;

    // cp.async mapping. A: 512 rows x 8 chunks(16B): thread t -> rows 2t,2t+1.
    //                   B:  64 rows x 8 chunks: thread t -> row t>>2, 2 chunks.
    const int b_row = tid >> 2;
    const int b_c0  = (tid & 3) * 2;

    auto load_stage = [&](int st, int j) {
        char* as = smem + st * STAGE_BYTES;
        char* bs = as + A_STAGE_BYTES;
#pragma unroll
        for (int r = 0; r < 2; r++) {
            const int row = tid * 2 + r;
            const char* ga = (const char*)(Abase + (size_t)row * KTOT + (size_t)j * BK);
            uint32_t da;
            asm("{ .reg .u64 t; cvta.to.shared.u64 t, %1; cvt.u32.u64 %0, t; }"
                : "=r"(da) : "l"(as + row * (LDK * 4)));
#pragma unroll
            for (int c = 0; c < 8; c++)
                asm volatile("cp.async.cg.shared.global [%0], [%1], 16;"
                             :: "r"(da + c * 16), "l"(ga + c * 16) : "memory");
        }
        const char* gb = (const char*)(Bbase + (size_t)b_row * KTOT + (size_t)j * BK);
        uint32_t db;
        asm("{ .reg .u64 t; cvta.to.shared.u64 t, %1; cvt.u32.u64 %0, t; }"
            : "=r"(db) : "l"(bs + b_row * (LDK * 4)));
#pragma unroll
        for (int c = 0; c < 2; c++)
            asm volatile("cp.async.cg.shared.global [%0], [%1], 16;"
                         :: "r"(db + (b_c0 + c) * 16), "l"(gb + (b_c0 + c) * 16) : "memory");
        asm volatile("cp.async.commit_group;" ::: "memory");
    };

    float acc[4][8][4];
#pragma unroll
    for (int mi = 0; mi < 4; mi++)
#pragma unroll
        for (int ni = 0; ni < 8; ni++)
#pragma unroll
            for (int r = 0; r < 4; r++) acc[mi][ni][r] = 0.f;

    // prologue: fill both buffers
    load_stage(0, 0);
    if (kcnt > 1) load_stage(1, 1);
    else          asm volatile("cp.async.commit_group;" ::: "memory");

    for (int i = 0; i < kcnt; i++) {
        const int s = i & 1;
        asm volatile("cp.async.wait_group 1;" ::: "memory");
        __syncthreads();

        const float* As = (const float*)(smem + s * STAGE_BYTES);
        const float* Bs = (const float*)(smem + s * STAGE_BYTES + A_STAGE_BYTES);

#pragma unroll
        for (int ks = 0; ks < 4; ks++) {
            const int k0 = ks * 8 + lc;
            uint32_t b[8][2];
#pragma unroll
            for (int ni = 0; ni < 8; ni++) {
                const int nbase = (ni * 8 + lr) * LDK;
                b[ni][0] = __float_as_uint(Bs[nbase + k0]);
                b[ni][1] = __float_as_uint(Bs[nbase + k0 + 4]);
            }
#pragma unroll
            for (int mi = 0; mi < 4; mi++) {
                const int rbase = (wid * 64 + mi * 16 + lr) * LDK;
                float f0v = As[rbase + k0];
                float f1v = As[rbase + 8 * LDK + k0];
                float f2v = As[rbase + k0 + 4];
                float f3v = As[rbase + 8 * LDK + k0 + 4];
                uint32_t a0, a1, a2, a3;
                asm("cvt.rna.tf32.f32 %0, %1;" : "=r"(a0) : "f"(f0v));
                asm("cvt.rna.tf32.f32 %0, %1;" : "=r"(a1) : "f"(f1v));
                asm("cvt.rna.tf32.f32 %0, %1;" : "=r"(a2) : "f"(f2v));
                asm("cvt.rna.tf32.f32 %0, %1;" : "=r"(a3) : "f"(f3v));
#pragma unroll
                for (int ni = 0; ni < 8; ni++)
                    asm("mma.sync.aligned.m16n8k8.row.col.f32.tf32.tf32.f32 "
                        "{%0,%1,%2,%3}, {%4,%5,%6,%7}, {%8,%9}, {%0,%1,%2,%3};"
                        : "+f"(acc[mi][ni][0]), "+f"(acc[mi][ni][1]),
                          "+f"(acc[mi][ni][2]), "+f"(acc[mi][ni][3])
                        : "r"(a0), "r"(a1), "r"(a2), "r"(a3),
                          "r"(b[ni][0]), "r"(b[ni][1]));
            }
        }
        __syncthreads();

        // trailing load: refill the buffer just consumed with iteration i+2
        const int j = i + 2;
        if (j < kcnt) load_stage(s, j);
        else asm volatile("cp.async.commit_group;" ::: "memory");
    }

    // epilogue: accumulators -> g_part
#pragma unroll
    for (int mi = 0; mi < 4; mi++)
#pragma unroll
        for (int h = 0; h < 2; h++) {
            const int m = m0 + wid * 64 + mi * 16 + h * 8 + lr;
            float* row = g_part + ((size_t)sp * A_ATOMS + m) * 64;
#pragma unroll
            for (int ni = 0; ni < 8; ni++) {
                const int col = ni * 8 + lc * 2;
                *(float2*)(row + col) =
                    make_float2(acc[mi][ni][h * 2], acc[mi][ni][h * 2 + 1]);
            }
        }
}

// ---------------------------------------------------------------------------
// reduce split-K partials + BC (+ residual) + ReLU
// ---------------------------------------------------------------------------
__global__ __launch_bounds__(256) void epi_kernel(int bc_idx,
                                                  const float* __restrict__ resid,
                                                  int to_gh, float* __restrict__ out,
                                                  int add_res)
{
    int i = blockIdx.x * 256 + threadIdx.x;
    float s = 0.f;
#pragma unroll
    for (int sp = 0; sp < NSPLIT; sp++)
        s += g_part[(size_t)sp * MN + i];
    s += g_BC[(size_t)bc_idx * MN + i];
    if (add_res) s += resid[i];
    s = fmaxf(s, 0.f);
    (to_gh ? g_h : out)[i] = s;
}

// ---------------------------------------------------------------------------
extern "C" void kernel_launch(void* const* d_in, const int* in_sizes, int n_in,
                              void* d_out, int out_size)
{
    const float* x    = (const float*)d_in[0];
    const float* conn = (const float*)d_in[1];
    const float* bond = (const float*)d_in[2];
    const float* f0   = (const float*)d_in[3];
    const float* f1   = (const float*)d_in[4];
    float* out = (float*)d_out;

    cudaFuncSetAttribute(gemm_mma, cudaFuncAttributeMaxDynamicSharedMemorySize, SMEM_DYN);

    dim3 gg(A_ATOMS / BM, NSPLIT);   // (4, 37) = 148 CTAs

    bc_kernel<<<A_ATOMS, 64>>>(bond, f0, f1);

    // layer 0, conv 1: h = relu(conv(x, f0))
    w2_kernel<<<256, 256>>>(0, x, f0);
    gemm_mma<<<gg, 256, SMEM_DYN>>>(conn);
    epi_kernel<<<MN / 256, 256>>>(0, x, 1, out, 0);

    // layer 0, conv 2: out0 = relu(conv(h, f0) + x)
    w2_kernel<<<256, 256>>>(1, x, f0);
    gemm_mma<<<gg, 256, SMEM_DYN>>>(conn);
    epi_kernel<<<MN / 256, 256>>>(0, x, 1, out, 1);

    // layer 1, conv 1: h = relu(conv(out0, f1))
    w2_kernel<<<256, 256>>>(1, x, f1);
    gemm_mma<<<gg, 256, SMEM_DYN>>>(conn);
    epi_kernel<<<MN / 256, 256>>>(1, x, 1, out, 0);

    // layer 1, conv 2: final = relu(conv(h, f1) + x)
    w2_kernel<<<256, 256>>>(1, x, f1);
    gemm_mma<<<gg, 256, SMEM_DYN>>>(conn);
    epi_kernel<<<MN / 256, 256>>>(1, x, 0, out, 1);
}

// round 13
// speedup vs baseline: 1.0642x; 1.0642x over previous
#include <cuda_runtime.h>
#include <cstdint>
#include <cstddef>

// ---------------- problem constants ----------------
#define A_ATOMS 2048
#define DEPTH   64
#define FILT    12
#define KTOT    24576          // A_ATOMS * FILT
#define MN      131072         // A_ATOMS * DEPTH

// ---------------- GEMM config ----------------
#define BM      128
#define BN      64
#define BK      32             // floats of K per stage
#define NSPLIT  18
#define STAGES  4

#define LDK     36             // padded row length (floats) -> 144 B
#define A_STAGE_BYTES (BM * LDK * 4)        // 18432
#define B_STAGE_BYTES (BN * LDK * 4)        // 9216
#define STAGE_BYTES   (A_STAGE_BYTES + B_STAGE_BYTES)  // 27648
#define SMEM_DYN      (STAGES * STAGE_BYTES)           // 110592

// ---------------- static scratch ----------------
__device__ float g_Wt[64 * KTOT];       // W^T [o][k], RN tf32-rounded
__device__ float g_part[NSPLIT * MN];   // split-K partials
__device__ float g_h[MN];               // activation buffer
__device__ float g_BC[2 * MN];          // bond contributions

// ---------------------------------------------------------------------------
// BC[l][a][o] = sum_{f,j} bond[a,f,j] * filters_l[o,f,64+j]
// ---------------------------------------------------------------------------
__global__ __launch_bounds__(64) void bc_kernel(const float* __restrict__ bond,
                                                const float* __restrict__ f0,
                                                const float* __restrict__ f1)
{
    int a = blockIdx.x;
    int o = threadIdx.x;
    __shared__ float bs[24];
    if (o < 24) bs[o] = bond[a * 24 + o];
    __syncthreads();
    float acc0 = 0.f, acc1 = 0.f;
#pragma unroll
    for (int f = 0; f < FILT; f++)
#pragma unroll
        for (int j = 0; j < 2; j++) {
            float b = bs[f * 2 + j];
            acc0 += b * f0[o * 792 + f * 66 + 64 + j];
            acc1 += b * f1[o * 792 + f * 66 + 64 + j];
        }
    g_BC[a * 64 + o]      = acc0;
    g_BC[MN + a * 64 + o] = acc1;
}

// ---------------------------------------------------------------------------
// W^T[o][n*12+f] = round_rn_tf32( sum_d z[n,d] * filt[o,f,d] )
// ---------------------------------------------------------------------------
__global__ __launch_bounds__(256) void w2_kernel(int zsel,
                                                 const float* __restrict__ x,
                                                 const float* __restrict__ filt)
{
    const float* z = zsel ? g_h : x;
    __shared__ float act[8][64];
    __shared__ float fs[64][65];
    __shared__ float outp[64][96];
    const int n0  = blockIdx.x * 8;
    const int tid = threadIdx.x;

    if (tid < 128) {
        int r = tid >> 4, d = (tid & 15) * 4;
        *(float4*)&act[r][d] = *(const float4*)(z + (size_t)(n0 + r) * 64 + d);
    }

    const int ol = tid & 31;
    const int nl = tid >> 5;
    float acc[12][2];

#pragma unroll 1
    for (int f = 0; f < 12; f++) {
        __syncthreads();
        {
            int o  = tid >> 2;
            int d0 = (tid & 3) * 16;
#pragma unroll
            for (int c = 0; c < 8; c++) {
                float2 v = *(const float2*)(filt + (size_t)o * 792 + f * 66 + d0 + c * 2);
                fs[o][d0 + c * 2]     = v.x;
                fs[o][d0 + c * 2 + 1] = v.y;
            }
        }
        __syncthreads();
        float a0 = 0.f, a1 = 0.f;
#pragma unroll 16
        for (int d = 0; d < 64; d++) {
            float av = act[nl][d];
            a0 = fmaf(av, fs[ol * 2][d], a0);
            a1 = fmaf(av, fs[ol * 2 + 1][d], a1);
        }
        acc[f][0] = a0;
        acc[f][1] = a1;
    }

    __syncthreads();
#pragma unroll
    for (int f = 0; f < 12; f++) {
        outp[ol * 2][nl * 12 + f]     = acc[f][0];
        outp[ol * 2 + 1][nl * 12 + f] = acc[f][1];
    }
    __syncthreads();

#pragma unroll
    for (int t = 0; t < 24; t++) {
        int idx = tid + t * 256;
        int row = idx / 96, col = idx % 96;
        float v = outp[row][col];
        uint32_t u;
        asm("cvt.rna.tf32.f32 %0, %1;" : "=r"(u) : "f"(v));
        g_Wt[(size_t)row * KTOT + n0 * 12 + col] = __uint_as_float(u);
    }
}

// ---------------------------------------------------------------------------
// Big GEMM, mma.sync tf32 m16n8k8, single term, A RNA-rounded in-register.
// MMA issue order: ni outer / mi inner so consecutive HMMAs SHARE the b
// fragment registers (R5-style operand reuse).
// grid (16 m-tiles, 18 k-splits), 256 threads (8 warps: 4M x 2N, 32x32 each),
// 4-stage cp.async pipeline, 2 CTAs/SM.
// ---------------------------------------------------------------------------
__global__ __launch_bounds__(256, 2) void gemm_mma(const float* __restrict__ Ag)
{
    extern __shared__ __align__(128) char smem[];

    const int tid  = threadIdx.x;
    const int wid  = tid >> 5;
    const int lane = tid & 31;
    const int wm   = wid & 3;
    const int wn   = wid >> 2;
    const int lr   = lane >> 2;
    const int lc   = lane & 3;

    const int sp   = blockIdx.y;
    const int kbeg = sp * 42 + (sp < 12 ? sp : 12);   // in BK units
    const int kcnt = 42 + (sp < 12 ? 1 : 0);
    const int m0   = blockIdx.x * BM;

    const float* Abase = Ag + (size_t)m0 * KTOT + (size_t)kbeg * BK;
    const float* Bbase = g_Wt + (size_t)kbeg * BK;

    const int a_row = tid >> 1;
    const int a_c0  = (tid & 1) * 4;
    const int b_row = tid >> 2;
    const int b_c0  = (tid & 3) * 2;

    auto load_stage = [&](int st, int j) {
        char* as = smem + st * STAGE_BYTES;
        char* bs = as + A_STAGE_BYTES;
        const char* ga = (const char*)(Abase + (size_t)a_row * KTOT + (size_t)j * BK);
        uint32_t da;
        asm("{ .reg .u64 t; cvta.to.shared.u64 t, %1; cvt.u32.u64 %0, t; }"
            : "=r"(da) : "l"(as + a_row * (LDK * 4)));
#pragma unroll
        for (int c = 0; c < 4; c++)
            asm volatile("cp.async.cg.shared.global [%0], [%1], 16;"
                         :: "r"(da + (a_c0 + c) * 16), "l"(ga + (a_c0 + c) * 16) : "memory");
        const char* gb = (const char*)(Bbase + (size_t)b_row * KTOT + (size_t)j * BK);
        uint32_t db;
        asm("{ .reg .u64 t; cvta.to.shared.u64 t, %1; cvt.u32.u64 %0, t; }"
            : "=r"(db) : "l"(bs + b_row * (LDK * 4)));
#pragma unroll
        for (int c = 0; c < 2; c++)
            asm volatile("cp.async.cg.shared.global [%0], [%1], 16;"
                         :: "r"(db + (b_c0 + c) * 16), "l"(gb + (b_c0 + c) * 16) : "memory");
        asm volatile("cp.async.commit_group;" ::: "memory");
    };

    float acc[2][4][4];
#pragma unroll
    for (int mi = 0; mi < 2; mi++)
#pragma unroll
        for (int ni = 0; ni < 4; ni++)
#pragma unroll
            for (int r = 0; r < 4; r++) acc[mi][ni][r] = 0.f;

    for (int j = 0; j < STAGES - 1; j++) load_stage(j, j);

    for (int i = 0; i < kcnt; i++) {
        const int s = i & (STAGES - 1);
        asm volatile("cp.async.wait_group %0;" :: "n"(STAGES - 2) : "memory");
        __syncthreads();

        const int j = i + STAGES - 1;
        if (j < kcnt) load_stage(j & (STAGES - 1), j);
        else asm volatile("cp.async.commit_group;" ::: "memory");

        const float* As = (const float*)(smem + s * STAGE_BYTES);
        const float* Bs = (const float*)(smem + s * STAGE_BYTES + A_STAGE_BYTES);

#pragma unroll
        for (int ks = 0; ks < 4; ks++) {
            const int k0 = ks * 8 + lc;
            uint32_t a[2][4], b[4][2];
#pragma unroll
            for (int mi = 0; mi < 2; mi++) {
                const int rbase = (wm * 32 + mi * 16 + lr) * LDK;
                float f0v = As[rbase + k0];
                float f1v = As[rbase + 8 * LDK + k0];
                float f2v = As[rbase + k0 + 4];
                float f3v = As[rbase + 8 * LDK + k0 + 4];
                asm("cvt.rna.tf32.f32 %0, %1;" : "=r"(a[mi][0]) : "f"(f0v));
                asm("cvt.rna.tf32.f32 %0, %1;" : "=r"(a[mi][1]) : "f"(f1v));
                asm("cvt.rna.tf32.f32 %0, %1;" : "=r"(a[mi][2]) : "f"(f2v));
                asm("cvt.rna.tf32.f32 %0, %1;" : "=r"(a[mi][3]) : "f"(f3v));
            }
#pragma unroll
            for (int ni = 0; ni < 4; ni++) {
                const int nbase = (wn * 32 + ni * 8 + lr) * LDK;
                b[ni][0] = __float_as_uint(Bs[nbase + k0]);
                b[ni][1] = __float_as_uint(Bs[nbase + k0 + 4]);
            }
            // ni outer / mi inner: consecutive HMMAs share b[ni]
#pragma unroll
            for (int ni = 0; ni < 4; ni++)
#pragma unroll
                for (int mi = 0; mi < 2; mi++)
                    asm("mma.sync.aligned.m16n8k8.row.col.f32.tf32.tf32.f32 "
                        "{%0,%1,%2,%3}, {%4,%5,%6,%7}, {%8,%9}, {%0,%1,%2,%3};"
                        : "+f"(acc[mi][ni][0]), "+f"(acc[mi][ni][1]),
                          "+f"(acc[mi][ni][2]), "+f"(acc[mi][ni][3])
                        : "r"(a[mi][0]), "r"(a[mi][1]), "r"(a[mi][2]), "r"(a[mi][3]),
                          "r"(b[ni][0]), "r"(b[ni][1]));
        }
        __syncthreads();
    }

    // epilogue: accumulators -> g_part
#pragma unroll
    for (int mi = 0; mi < 2; mi++)
#pragma unroll
        for (int h = 0; h < 2; h++) {
            const int m = m0 + wm * 32 + mi * 16 + h * 8 + lr;
            float* row = g_part + ((size_t)sp * A_ATOMS + m) * 64;
#pragma unroll
            for (int ni = 0; ni < 4; ni++) {
                const int col = wn * 32 + ni * 8 + lc * 2;
                *(float2*)(row + col) =
                    make_float2(acc[mi][ni][h * 2], acc[mi][ni][h * 2 + 1]);
            }
        }
}

// ---------------------------------------------------------------------------
// reduce split-K partials + BC (+ residual) + ReLU
// ---------------------------------------------------------------------------
__global__ __launch_bounds__(256) void epi_kernel(int bc_idx,
                                                  const float* __restrict__ resid,
                                                  int to_gh, float* __restrict__ out,
                                                  int add_res)
{
    int i = blockIdx.x * 256 + threadIdx.x;
    float s = 0.f;
#pragma unroll
    for (int sp = 0; sp < NSPLIT; sp++)
        s += g_part[(size_t)sp * MN + i];
    s += g_BC[(size_t)bc_idx * MN + i];
    if (add_res) s += resid[i];
    s = fmaxf(s, 0.f);
    (to_gh ? g_h : out)[i] = s;
}

// ---------------------------------------------------------------------------
extern "C" void kernel_launch(void* const* d_in, const int* in_sizes, int n_in,
                              void* d_out, int out_size)
{
    const float* x    = (const float*)d_in[0];
    const float* conn = (const float*)d_in[1];
    const float* bond = (const float*)d_in[2];
    const float* f0   = (const float*)d_in[3];
    const float* f1   = (const float*)d_in[4];
    float* out = (float*)d_out;

    cudaFuncSetAttribute(gemm_mma, cudaFuncAttributeMaxDynamicSharedMemorySize, SMEM_DYN);

    dim3 gg(A_ATOMS / BM, NSPLIT);

    bc_kernel<<<A_ATOMS, 64>>>(bond, f0, f1);

    // layer 0, conv 1: h = relu(conv(x, f0))
    w2_kernel<<<256, 256>>>(0, x, f0);
    gemm_mma<<<gg, 256, SMEM_DYN>>>(conn);
    epi_kernel<<<MN / 256, 256>>>(0, x, 1, out, 0);

    // layer 0, conv 2: out0 = relu(conv(h, f0) + x)
    w2_kernel<<<256, 256>>>(1, x, f0);
    gemm_mma<<<gg, 256, SMEM_DYN>>>(conn);
    epi_kernel<<<MN / 256, 256>>>(0, x, 1, out, 1);

    // layer 1, conv 1: h = relu(conv(out0, f1))
    w2_kernel<<<256, 256>>>(1, x, f1);
    gemm_mma<<<gg, 256, SMEM_DYN>>>(conn);
    epi_kernel<<<MN / 256, 256>>>(1, x, 1, out, 0);

    // layer 1, conv 2: final = relu(conv(h, f1) + x)
    w2_kernel<<<256, 256>>>(1, x, f1);
    gemm_mma<<<gg, 256, SMEM_DYN>>>(conn);
    epi_kernel<<<MN / 256, 256>>>(1, x, 0, out, 1);
}

// round 14
// speedup vs baseline: 1.0741x; 1.0094x over previous
#include <cuda_runtime.h>
#include <cstdint>
#include <cstddef>

// ---------------- problem constants ----------------
#define A_ATOMS 2048
#define DEPTH   64
#define FILT    12
#define KTOT    24576          // A_ATOMS * FILT
#define MN      131072         // A_ATOMS * DEPTH

// ---------------- GEMM config ----------------
#define BM      128
#define BN      64
#define BK      32             // floats of K per stage
#define NSPLIT  18             // grid splits; effective = 36 (x2 intra-CTA)
#define NSLOT   36
#define STAGES  4

#define LDK     36             // padded row length (floats) -> 144 B
#define A_STAGE_BYTES (BM * LDK * 4)        // 18432
#define B_STAGE_BYTES (BN * LDK * 4)        // 9216
#define STAGE_BYTES   (A_STAGE_BYTES + B_STAGE_BYTES)  // 27648
#define SMEM_DYN      (STAGES * STAGE_BYTES)           // 110592

// ---------------- static scratch ----------------
__device__ float g_Wt[64 * KTOT];       // W^T [o][k], RN tf32-rounded
__device__ float g_part[NSLOT * MN];    // split-K partials (18.9 MB)
__device__ float g_h[MN];               // activation buffer
__device__ float g_BC[2 * MN];          // bond contributions

// ---------------------------------------------------------------------------
// BC[l][a][o] = sum_{f,j} bond[a,f,j] * filters_l[o,f,64+j]
// ---------------------------------------------------------------------------
__global__ __launch_bounds__(64) void bc_kernel(const float* __restrict__ bond,
                                                const float* __restrict__ f0,
                                                const float* __restrict__ f1)
{
    int a = blockIdx.x;
    int o = threadIdx.x;
    __shared__ float bs[24];
    if (o < 24) bs[o] = bond[a * 24 + o];
    __syncthreads();
    float acc0 = 0.f, acc1 = 0.f;
#pragma unroll
    for (int f = 0; f < FILT; f++)
#pragma unroll
        for (int j = 0; j < 2; j++) {
            float b = bs[f * 2 + j];
            acc0 += b * f0[o * 792 + f * 66 + 64 + j];
            acc1 += b * f1[o * 792 + f * 66 + 64 + j];
        }
    g_BC[a * 64 + o]      = acc0;
    g_BC[MN + a * 64 + o] = acc1;
}

// ---------------------------------------------------------------------------
// W^T[o][n*12+f] = round_rn_tf32( sum_d z[n,d] * filt[o,f,d] )
// ---------------------------------------------------------------------------
__global__ __launch_bounds__(256) void w2_kernel(int zsel,
                                                 const float* __restrict__ x,
                                                 const float* __restrict__ filt)
{
    const float* z = zsel ? g_h : x;
    __shared__ float act[8][64];
    __shared__ float fs[64][65];
    __shared__ float outp[64][96];
    const int n0  = blockIdx.x * 8;
    const int tid = threadIdx.x;

    if (tid < 128) {
        int r = tid >> 4, d = (tid & 15) * 4;
        *(float4*)&act[r][d] = *(const float4*)(z + (size_t)(n0 + r) * 64 + d);
    }

    const int ol = tid & 31;
    const int nl = tid >> 5;
    float acc[12][2];

#pragma unroll 1
    for (int f = 0; f < 12; f++) {
        __syncthreads();
        {
            int o  = tid >> 2;
            int d0 = (tid & 3) * 16;
#pragma unroll
            for (int c = 0; c < 8; c++) {
                float2 v = *(const float2*)(filt + (size_t)o * 792 + f * 66 + d0 + c * 2);
                fs[o][d0 + c * 2]     = v.x;
                fs[o][d0 + c * 2 + 1] = v.y;
            }
        }
        __syncthreads();
        float a0 = 0.f, a1 = 0.f;
#pragma unroll 16
        for (int d = 0; d < 64; d++) {
            float av = act[nl][d];
            a0 = fmaf(av, fs[ol * 2][d], a0);
            a1 = fmaf(av, fs[ol * 2 + 1][d], a1);
        }
        acc[f][0] = a0;
        acc[f][1] = a1;
    }

    __syncthreads();
#pragma unroll
    for (int f = 0; f < 12; f++) {
        outp[ol * 2][nl * 12 + f]     = acc[f][0];
        outp[ol * 2 + 1][nl * 12 + f] = acc[f][1];
    }
    __syncthreads();

#pragma unroll
    for (int t = 0; t < 24; t++) {
        int idx = tid + t * 256;
        int row = idx / 96, col = idx % 96;
        float v = outp[row][col];
        uint32_t u;
        asm("cvt.rna.tf32.f32 %0, %1;" : "=r"(u) : "f"(v));
        g_Wt[(size_t)row * KTOT + n0 * 12 + col] = __uint_as_float(u);
    }
}

// ---------------------------------------------------------------------------
// Big GEMM, mma.sync tf32 m16n8k8, single term, A RNA-rounded in-register.
// Intra-CTA split-K: 8 warps, warp tile 32x64; warp group g = wid>>2 handles
// ks in {2g, 2g+1} of each BK=32 stage -> 16 HMMA per fragment window
// (R5's saturating window shape) at 16 warps/SM. Group g writes split slot
// sp*2+g; epi reduces 36 slots.
// ---------------------------------------------------------------------------
__global__ __launch_bounds__(256, 2) void gemm_mma(const float* __restrict__ Ag)
{
    extern __shared__ __align__(128) char smem[];

    const int tid  = threadIdx.x;
    const int wid  = tid >> 5;
    const int lane = tid & 31;
    const int g    = wid >> 2;       // k-half group (0 or 1)
    const int wm   = wid & 3;        // warp row tile (32 rows each)
    const int lr   = lane >> 2;      // 0..7
    const int lc   = lane & 3;       // 0..3

    const int sp   = blockIdx.y;
    const int kbeg = sp * 42 + (sp < 12 ? sp : 12);   // in BK units
    const int kcnt = 42 + (sp < 12 ? 1 : 0);
    const int m0   = blockIdx.x * BM;

    const float* Abase = Ag + (size_t)m0 * KTOT + (size_t)kbeg * BK;
    const float* Bbase = g_Wt + (size_t)kbeg * BK;

    const int a_row = tid >> 1;
    const int a_c0  = (tid & 1) * 4;
    const int b_row = tid >> 2;
    const int b_c0  = (tid & 3) * 2;

    auto load_stage = [&](int st, int j) {
        char* as = smem + st * STAGE_BYTES;
        char* bs = as + A_STAGE_BYTES;
        const char* ga = (const char*)(Abase + (size_t)a_row * KTOT + (size_t)j * BK);
        uint32_t da;
        asm("{ .reg .u64 t; cvta.to.shared.u64 t, %1; cvt.u32.u64 %0, t; }"
            : "=r"(da) : "l"(as + a_row * (LDK * 4)));
#pragma unroll
        for (int c = 0; c < 4; c++)
            asm volatile("cp.async.cg.shared.global [%0], [%1], 16;"
                         :: "r"(da + (a_c0 + c) * 16), "l"(ga + (a_c0 + c) * 16) : "memory");
        const char* gb = (const char*)(Bbase + (size_t)b_row * KTOT + (size_t)j * BK);
        uint32_t db;
        asm("{ .reg .u64 t; cvta.to.shared.u64 t, %1; cvt.u32.u64 %0, t; }"
            : "=r"(db) : "l"(bs + b_row * (LDK * 4)));
#pragma unroll
        for (int c = 0; c < 2; c++)
            asm volatile("cp.async.cg.shared.global [%0], [%1], 16;"
                         :: "r"(db + (b_c0 + c) * 16), "l"(gb + (b_c0 + c) * 16) : "memory");
        asm volatile("cp.async.commit_group;" ::: "memory");
    };

    float acc[2][8][4];
#pragma unroll
    for (int mi = 0; mi < 2; mi++)
#pragma unroll
        for (int ni = 0; ni < 8; ni++)
#pragma unroll
            for (int r = 0; r < 4; r++) acc[mi][ni][r] = 0.f;

    for (int j = 0; j < STAGES - 1; j++) load_stage(j, j);

    for (int i = 0; i < kcnt; i++) {
        const int s = i & (STAGES - 1);
        asm volatile("cp.async.wait_group %0;" :: "n"(STAGES - 2) : "memory");
        __syncthreads();

        const int j = i + STAGES - 1;
        if (j < kcnt) load_stage(j & (STAGES - 1), j);
        else asm volatile("cp.async.commit_group;" ::: "memory");

        const float* As = (const float*)(smem + s * STAGE_BYTES);
        const float* Bs = (const float*)(smem + s * STAGE_BYTES + A_STAGE_BYTES);

        // each warp handles its group's 2 ks-steps; 16 HMMA per window
#pragma unroll
        for (int w = 0; w < 2; w++) {
            const int ks = g * 2 + w;
            const int k0 = ks * 8 + lc;
            uint32_t a[2][4], b[8][2];
#pragma unroll
            for (int mi = 0; mi < 2; mi++) {
                const int rbase = (wm * 32 + mi * 16 + lr) * LDK;
                float f0v = As[rbase + k0];
                float f1v = As[rbase + 8 * LDK + k0];
                float f2v = As[rbase + k0 + 4];
                float f3v = As[rbase + 8 * LDK + k0 + 4];
                asm("cvt.rna.tf32.f32 %0, %1;" : "=r"(a[mi][0]) : "f"(f0v));
                asm("cvt.rna.tf32.f32 %0, %1;" : "=r"(a[mi][1]) : "f"(f1v));
                asm("cvt.rna.tf32.f32 %0, %1;" : "=r"(a[mi][2]) : "f"(f2v));
                asm("cvt.rna.tf32.f32 %0, %1;" : "=r"(a[mi][3]) : "f"(f3v));
            }
#pragma unroll
            for (int ni = 0; ni < 8; ni++) {
                const int nbase = (ni * 8 + lr) * LDK;
                b[ni][0] = __float_as_uint(Bs[nbase + k0]);
                b[ni][1] = __float_as_uint(Bs[nbase + k0 + 4]);
            }
#pragma unroll
            for (int ni = 0; ni < 8; ni++)
#pragma unroll
                for (int mi = 0; mi < 2; mi++)
                    asm("mma.sync.aligned.m16n8k8.row.col.f32.tf32.tf32.f32 "
                        "{%0,%1,%2,%3}, {%4,%5,%6,%7}, {%8,%9}, {%0,%1,%2,%3};"
                        : "+f"(acc[mi][ni][0]), "+f"(acc[mi][ni][1]),
                          "+f"(acc[mi][ni][2]), "+f"(acc[mi][ni][3])
                        : "r"(a[mi][0]), "r"(a[mi][1]), "r"(a[mi][2]), "r"(a[mi][3]),
                          "r"(b[ni][0]), "r"(b[ni][1]));
        }
        __syncthreads();
    }

    // epilogue: accumulators -> g_part slot sp*2+g
#pragma unroll
    for (int mi = 0; mi < 2; mi++)
#pragma unroll
        for (int h = 0; h < 2; h++) {
            const int m = m0 + wm * 32 + mi * 16 + h * 8 + lr;
            float* row = g_part + ((size_t)(sp * 2 + g) * A_ATOMS + m) * 64;
#pragma unroll
            for (int ni = 0; ni < 8; ni++) {
                const int col = ni * 8 + lc * 2;
                *(float2*)(row + col) =
                    make_float2(acc[mi][ni][h * 2], acc[mi][ni][h * 2 + 1]);
            }
        }
}

// ---------------------------------------------------------------------------
// reduce split-K partials + BC (+ residual) + ReLU
// ---------------------------------------------------------------------------
__global__ __launch_bounds__(256) void epi_kernel(int bc_idx,
                                                  const float* __restrict__ resid,
                                                  int to_gh, float* __restrict__ out,
                                                  int add_res)
{
    int i = blockIdx.x * 256 + threadIdx.x;
    float s = 0.f;
#pragma unroll
    for (int sp = 0; sp < NSLOT; sp++)
        s += g_part[(size_t)sp * MN + i];
    s += g_BC[(size_t)bc_idx * MN + i];
    if (add_res) s += resid[i];
    s = fmaxf(s, 0.f);
    (to_gh ? g_h : out)[i] = s;
}

// ---------------------------------------------------------------------------
extern "C" void kernel_launch(void* const* d_in, const int* in_sizes, int n_in,
                              void* d_out, int out_size)
{
    const float* x    = (const float*)d_in[0];
    const float* conn = (const float*)d_in[1];
    const float* bond = (const float*)d_in[2];
    const float* f0   = (const float*)d_in[3];
    const float* f1   = (const float*)d_in[4];
    float* out = (float*)d_out;

    cudaFuncSetAttribute(gemm_mma, cudaFuncAttributeMaxDynamicSharedMemorySize, SMEM_DYN);

    dim3 gg(A_ATOMS / BM, NSPLIT);

    bc_kernel<<<A_ATOMS, 64>>>(bond, f0, f1);

    // layer 0, conv 1: h = relu(conv(x, f0))
    w2_kernel<<<256, 256>>>(0, x, f0);
    gemm_mma<<<gg, 256, SMEM_DYN>>>(conn);
    epi_kernel<<<MN / 256, 256>>>(0, x, 1, out, 0);

    // layer 0, conv 2: out0 = relu(conv(h, f0) + x)
    w2_kernel<<<256, 256>>>(1, x, f0);
    gemm_mma<<<gg, 256, SMEM_DYN>>>(conn);
    epi_kernel<<<MN / 256, 256>>>(0, x, 1, out, 1);

    // layer 1, conv 1: h = relu(conv(out0, f1))
    w2_kernel<<<256, 256>>>(1, x, f1);
    gemm_mma<<<gg, 256, SMEM_DYN>>>(conn);
    epi_kernel<<<MN / 256, 256>>>(1, x, 1, out, 0);

    // layer 1, conv 2: final = relu(conv(h, f1) + x)
    w2_kernel<<<256, 256>>>(1, x, f1);
    gemm_mma<<<gg, 256, SMEM_DYN>>>(conn);
    epi_kernel<<<MN / 256, 256>>>(1, x, 0, out, 1);
}